// round 17
// baseline (speedup 1.0000x reference)
#include <cuda_runtime.h>
#include <cuda_bf16.h>
#include <math.h>
#include <stdint.h>

#define BSZ 16
#define CDIM 512
#define HWD 1024   // 32*32
#define QB  4      // quarter batch (chunk size)

// ---------------- device scratch (allocation-guard safe) -------------------
__device__ __nv_bfloat16  g_xb [BSZ * CDIM * HWD];           // x bf16 [b][c][i]
__device__ __nv_bfloat16  g_qkv[BSZ * 3 * CDIM * HWD];       // q|k|v [b][3c][i]
__device__ __nv_bfloat16  g_ab [BSZ * HWD * HWD];            // unnormalized P bf16
__device__ __nv_bfloat16  g_ob [BSZ * CDIM * HWD];           // attn@V bf16 [b][c][i]
__device__ __nv_bfloat16  g_w  [4][CDIM * CDIM];             // Wq|Wk|Wv (1536x512), Wo
__device__ float          g_bqkv[3 * CDIM];                  // packed bq|bk|bv
__device__ float          g_part[BSZ * HWD * 16];            // row-sum partials
__device__ float          g_inv [BSZ * HWD];                 // 1/rowsum

// ---------------- small helpers --------------------------------------------
__device__ __forceinline__ uint32_t packbf(float lo, float hi) {
    uint32_t r;
    asm("cvt.rn.bf16x2.f32 %0, %1, %2;" : "=r"(r) : "f"(hi), "f"(lo));
    return r;
}
__device__ __forceinline__ void ldm4(uint32_t r[4], uint32_t addr) {
    asm volatile("ldmatrix.sync.aligned.m8n8.x4.shared.b16 {%0,%1,%2,%3}, [%4];"
                 : "=r"(r[0]), "=r"(r[1]), "=r"(r[2]), "=r"(r[3]) : "r"(addr));
}
__device__ __forceinline__ void ldm4t(uint32_t r[4], uint32_t addr) {
    asm volatile("ldmatrix.sync.aligned.m8n8.x4.trans.shared.b16 {%0,%1,%2,%3}, [%4];"
                 : "=r"(r[0]), "=r"(r[1]), "=r"(r[2]), "=r"(r[3]) : "r"(addr));
}
__device__ __forceinline__ void mma_bf16(float c[4], const uint32_t a[4], const uint32_t b[2]) {
    asm volatile(
        "mma.sync.aligned.m16n8k16.row.col.f32.bf16.bf16.f32 "
        "{%0,%1,%2,%3}, {%4,%5,%6,%7}, {%8,%9}, {%0,%1,%2,%3};\n"
        : "+f"(c[0]), "+f"(c[1]), "+f"(c[2]), "+f"(c[3])
        : "r"(a[0]), "r"(a[1]), "r"(a[2]), "r"(a[3]), "r"(b[0]), "r"(b[1]));
}
__device__ __forceinline__ void cpa16(uint32_t dst, const void* src) {
    asm volatile("cp.async.cg.shared.global [%0], [%1], 16;" :: "r"(dst), "l"(src));
}
#define CP_COMMIT() asm volatile("cp.async.commit_group;" ::: "memory")
#define CP_WAIT1()  asm volatile("cp.async.wait_group 1;" ::: "memory")
#define CP_WAIT0()  asm volatile("cp.async.wait_group 0;" ::: "memory")

// ---------------------------------------------------------------------------
// Weight convert (4x512x512 f32->bf16) + bias pack. grid = 1024 x 256.
// ---------------------------------------------------------------------------
__global__ __launch_bounds__(256)
void wbias_kernel(const float4* __restrict__ w0, const float4* __restrict__ w1,
                  const float4* __restrict__ w2, const float4* __restrict__ w3,
                  const float* __restrict__ bq, const float* __restrict__ bk,
                  const float* __restrict__ bv,
                  uint2* __restrict__ wdst, float* __restrict__ bias)
{
    const int gid = blockIdx.x * 256 + threadIdx.x;    // < 262144

    if (gid < 3 * CDIM)
        bias[gid] = gid < CDIM ? bq[gid]
                  : gid < 2 * CDIM ? bk[gid - CDIM] : bv[gid - 2 * CDIM];

    const int which = gid >> 16, i = gid & 65535;
    const float4* src = which == 0 ? w0 : which == 1 ? w1
                      : which == 2 ? w2 : w3;
    float4 v = src[i];
    uint2 o;
    o.x = packbf(v.x, v.y);
    o.y = packbf(v.z, v.w);
    wdst[gid] = o;
}

// x convert for one batch chunk: n4 float4 starting at given pointers.
__global__ __launch_bounds__(256)
void xcvt_kernel(const float4* __restrict__ src, uint2* __restrict__ dst, int n4)
{
    for (int i = blockIdx.x * 256 + threadIdx.x; i < n4; i += gridDim.x * 256) {
        float4 v = src[i];
        uint2 o;
        o.x = packbf(v.x, v.y);
        o.y = packbf(v.z, v.w);
        dst[i] = o;
    }
}

// ---------------------------------------------------------------------------
// Batched bf16 tensor-core GEMM (round-11 engine, unchanged).
// MODE 0: plain; MODE 1: exp()+row-sum partials; MODE 2: *1/rowsum.
// ---------------------------------------------------------------------------
template<bool A_KC, bool B_NC, int LDA, int LDB, bool BIAS, bool RESID,
         bool OUT_F32, int MODE>
__global__ __launch_bounds__(128, 2)
void gemm_bf16(const __nv_bfloat16* __restrict__ A,
               const __nv_bfloat16* __restrict__ B,
               void* __restrict__ Cv, int K,
               long baA, long baB, long baC,
               float alpha, const float* __restrict__ bias,
               const float* __restrict__ resid, long baR,
               float* __restrict__ aux)
{
    extern __shared__ uint8_t smem[];
    const uint32_t smem_u = (uint32_t)__cvta_generic_to_shared(smem);
    const int STAGE = 32768;            // 16KB A + 16KB B

    const int b = blockIdx.z;
    A += (long)b * baA;
    B += (long)b * baB;
    if (RESID) resid += (long)b * baR;

    const int tid  = threadIdx.x;
    const int lane = tid & 31;
    const int wid  = tid >> 5;          // 0..3
    const int m0   = blockIdx.y * 128;
    const int n0   = blockIdx.x * 128;
    const int wm0  = (wid >> 1) * 64;   // 0 or 64
    const int wn0  = (wid & 1) * 64;    // 0 or 64

    float acc[4][8][4];
    #pragma unroll
    for (int i = 0; i < 4; ++i)
        #pragma unroll
        for (int j = 0; j < 8; ++j)
            #pragma unroll
            for (int r = 0; r < 4; ++r) acc[i][j][r] = 0.f;

    auto fill = [&](int kt, int buf) {
        const int k0 = kt * 64;
        const uint32_t Ab = smem_u + buf * STAGE;
        const uint32_t Bb = Ab + 16384;
        #pragma unroll
        for (int i = 0; i < 8; ++i) {
            const int g = tid + i * 128;
            if (A_KC) {
                const int m = g >> 3, u = g & 7;
                cpa16(Ab + m * 128 + ((u ^ (m & 7)) << 4),
                      A + (long)(m0 + m) * LDA + k0 + u * 8);
            } else {
                const int kk = g >> 4, u = g & 15;
                cpa16(Ab + kk * 256 + ((u ^ (kk & 7)) << 4),
                      A + (long)(k0 + kk) * LDA + m0 + u * 8);
            }
            if (B_NC) {
                const int kk = g >> 4, u = g & 15;
                cpa16(Bb + kk * 256 + ((u ^ (kk & 7)) << 4),
                      B + (long)(k0 + kk) * LDB + n0 + u * 8);
            } else {
                const int n = g >> 3, u = g & 7;
                cpa16(Bb + n * 128 + ((u ^ (n & 7)) << 4),
                      B + (long)(n0 + n) * LDB + k0 + u * 8);
            }
        }
        CP_COMMIT();
    };

    auto loadB = [&](uint32_t Bb, int s, int tb, uint32_t r[4]) {
        if (B_NC) {
            const int k_row = s * 16 + (lane & 7) + ((lane >> 3) & 1) * 8;
            const int u = ((wn0 + tb * 16) >> 3) + ((lane >> 4) & 1);
            ldm4t(r, Bb + k_row * 256 + ((u ^ (k_row & 7)) << 4));
        } else {
            const int n_row = wn0 + tb * 16 + (lane & 7) + ((lane >> 4) & 1) * 8;
            const int u = 2 * s + ((lane >> 3) & 1);
            ldm4(r, Bb + n_row * 128 + ((u ^ (n_row & 7)) << 4));
        }
    };

    auto compute = [&](int buf) {
        const uint32_t Ab = smem_u + buf * STAGE;
        const uint32_t Bb = Ab + 16384;
        #pragma unroll
        for (int s = 0; s < 4; ++s) {
            uint32_t af[4][4];
            #pragma unroll
            for (int tm = 0; tm < 4; ++tm) {
                if (A_KC) {
                    const int m_row = wm0 + tm * 16 + (lane & 15);
                    const int u = 2 * s + (lane >> 4);
                    ldm4(af[tm], Ab + m_row * 128 + ((u ^ (m_row & 7)) << 4));
                } else {
                    const int k_row = s * 16 + (lane & 7) + ((lane >> 4) & 1) * 8;
                    const int u = ((wm0 + tm * 16) >> 3) + ((lane >> 3) & 1);
                    ldm4t(af[tm], Ab + k_row * 256 + ((u ^ (k_row & 7)) << 4));
                }
            }
            uint32_t rb[2][4];
            loadB(Bb, s, 0, rb[0]);
            #pragma unroll
            for (int tb = 0; tb < 4; ++tb) {
                if (tb < 3) loadB(Bb, s, tb + 1, rb[(tb + 1) & 1]);
                const uint32_t* r = rb[tb & 1];
                uint32_t b0[2] = { r[0], r[1] };
                uint32_t b1[2] = { r[2], r[3] };
                #pragma unroll
                for (int tm = 0; tm < 4; ++tm) {
                    mma_bf16(acc[tm][tb * 2],     af[tm], b0);
                    mma_bf16(acc[tm][tb * 2 + 1], af[tm], b1);
                }
            }
        }
    };

    const int nkt = K >> 6;
    fill(0, 0);
    if (nkt > 1) fill(1, 1);

    for (int kt = 0; kt < nkt; ++kt) {
        if (kt == nkt - 1) { CP_WAIT0(); } else { CP_WAIT1(); }
        __syncthreads();
        if (kt + 2 < nkt) fill(kt + 2, (kt + 2) % 3);
        compute(kt % 3);
    }

    // ---- epilogue ----
    const int kq = lane & 3;
    const int mq = lane >> 2;

    float invs[16];
    if (MODE == 2) {
        #pragma unroll
        for (int tn = 0; tn < 8; ++tn) {
            const int n = n0 + wn0 + tn * 8 + 2 * kq;
            invs[tn * 2]     = aux[(long)b * HWD + n];
            invs[tn * 2 + 1] = aux[(long)b * HWD + n + 1];
        }
    }

    #pragma unroll
    for (int tm = 0; tm < 4; ++tm) {
        const int mA = m0 + wm0 + tm * 16 + mq;
        const int mB = mA + 8;
        if (MODE == 1) {
            __nv_bfloat16* C = (__nv_bfloat16*)Cv + (long)b * baC;
            float sA = 0.f, sB = 0.f;
            #pragma unroll
            for (int tn = 0; tn < 8; ++tn) {
                const int n = n0 + wn0 + tn * 8 + 2 * kq;
                float e0 = __expf(alpha * acc[tm][tn][0]);
                float e1 = __expf(alpha * acc[tm][tn][1]);
                float e2 = __expf(alpha * acc[tm][tn][2]);
                float e3 = __expf(alpha * acc[tm][tn][3]);
                sA += e0 + e1;
                sB += e2 + e3;
                *(uint32_t*)&C[(long)mA * HWD + n] = packbf(e0, e1);
                *(uint32_t*)&C[(long)mB * HWD + n] = packbf(e2, e3);
            }
            sA += __shfl_xor_sync(0xFFFFFFFFu, sA, 1);
            sA += __shfl_xor_sync(0xFFFFFFFFu, sA, 2);
            sB += __shfl_xor_sync(0xFFFFFFFFu, sB, 1);
            sB += __shfl_xor_sync(0xFFFFFFFFu, sB, 2);
            if (kq == 0) {
                const int jt2 = blockIdx.x * 2 + (wid & 1);
                aux[((long)b * HWD + mA) * 16 + jt2] = sA;
                aux[((long)b * HWD + mB) * 16 + jt2] = sB;
            }
        } else {
            const float biA = BIAS ? bias[mA] : 0.f;
            const float biB = BIAS ? bias[mB] : 0.f;
            #pragma unroll
            for (int tn = 0; tn < 8; ++tn) {
                const int n = n0 + wn0 + tn * 8 + 2 * kq;
                float v0 = alpha * acc[tm][tn][0] + biA;
                float v1 = alpha * acc[tm][tn][1] + biA;
                float v2 = alpha * acc[tm][tn][2] + biB;
                float v3 = alpha * acc[tm][tn][3] + biB;
                if (MODE == 2) {
                    v0 *= invs[tn * 2];     v1 *= invs[tn * 2 + 1];
                    v2 *= invs[tn * 2];     v3 *= invs[tn * 2 + 1];
                }
                if (RESID) {
                    const float2 rA = *(const float2*)&resid[(long)mA * HWD + n];
                    const float2 rB = *(const float2*)&resid[(long)mB * HWD + n];
                    v0 += rA.x; v1 += rA.y; v2 += rB.x; v3 += rB.y;
                }
                if (OUT_F32) {
                    float* C = (float*)Cv + (long)b * baC;
                    *(float2*)&C[(long)mA * HWD + n] = make_float2(v0, v1);
                    *(float2*)&C[(long)mB * HWD + n] = make_float2(v2, v3);
                } else {
                    __nv_bfloat16* C = (__nv_bfloat16*)Cv + (long)b * baC;
                    *(uint32_t*)&C[(long)mA * HWD + n] = packbf(v0, v1);
                    *(uint32_t*)&C[(long)mB * HWD + n] = packbf(v2, v3);
                }
            }
        }
    }
}

// Reduce 16 partials per row -> 1/rowsum.
__global__ __launch_bounds__(256)
void rowsum_inv_kernel(const float4* __restrict__ part, float* __restrict__ inv)
{
    const int i = blockIdx.x * 256 + threadIdx.x;
    float4 a = part[i * 4 + 0];
    float4 b = part[i * 4 + 1];
    float4 c = part[i * 4 + 2];
    float4 d = part[i * 4 + 3];
    float s = (a.x + a.y + a.z + a.w) + (b.x + b.y + b.z + b.w)
            + (c.x + c.y + c.z + c.w) + (d.x + d.y + d.z + d.w);
    inv[i] = 1.f / s;
}

// ---------------------------------------------------------------------------
extern "C" void kernel_launch(void* const* d_in, const int* in_sizes, int n_in,
                              void* d_out, int out_size)
{
    const float* x  = (const float*)d_in[0];
    const float* Wq = (const float*)d_in[1];
    const float* bq = (const float*)d_in[2];
    const float* Wk = (const float*)d_in[3];
    const float* bk = (const float*)d_in[4];
    const float* Wv = (const float*)d_in[5];
    const float* bv = (const float*)d_in[6];
    const float* Wo = (const float*)d_in[7];
    const float* bo = (const float*)d_in[8];
    float* out = (float*)d_out;

    float *bqkv, *part, *inv;
    __nv_bfloat16 *xb, *qkv, *ab, *ob, *wbase;
    cudaGetSymbolAddress((void**)&xb,   g_xb);
    cudaGetSymbolAddress((void**)&qkv,  g_qkv);
    cudaGetSymbolAddress((void**)&ab,   g_ab);
    cudaGetSymbolAddress((void**)&ob,   g_ob);
    cudaGetSymbolAddress((void**)&wbase, g_w);
    cudaGetSymbolAddress((void**)&bqkv, g_bqkv);
    cudaGetSymbolAddress((void**)&part, g_part);
    cudaGetSymbolAddress((void**)&inv,  g_inv);
    __nv_bfloat16* wqkv = wbase;                     // Wq|Wk|Wv = [1536][512]
    __nv_bfloat16* wo   = wbase + 3 * CDIM * CDIM;

    const long CHW  = (long)CDIM * HWD;
    const long QKVB = 3 * CHW;
    const long SHW  = (long)HWD * HWD;
    const int  SMEM = 3 * 32768;
    const dim3 blk(128);
    const float alpha = 1.0f / sqrtf((float)CDIM);

    auto kProj  = gemm_bf16<true,  true,  CDIM, HWD, true,  false, false, 0>;
    auto kScore = gemm_bf16<false, true,  HWD,  HWD, false, false, false, 1>;
    auto kAV    = gemm_bf16<true,  false, HWD,  HWD, false, false, false, 2>;
    auto kOut   = gemm_bf16<true,  true,  CDIM, HWD, true,  true,  true,  0>;
    cudaFuncSetAttribute(kProj,  cudaFuncAttributeMaxDynamicSharedMemorySize, SMEM);
    cudaFuncSetAttribute(kScore, cudaFuncAttributeMaxDynamicSharedMemorySize, SMEM);
    cudaFuncSetAttribute(kAV,    cudaFuncAttributeMaxDynamicSharedMemorySize, SMEM);
    cudaFuncSetAttribute(kOut,   cudaFuncAttributeMaxDynamicSharedMemorySize, SMEM);

    // Fork/join plumbing: created ONCE during the uncaptured correctness call;
    // reused, never destroyed. s1 == stream handle 0 (same default stream the
    // <<<>>> launches resolve to); s2 joins the capture via the fork event.
    static cudaStream_t s2 = nullptr;
    static cudaEvent_t evW = nullptr, evEnd = nullptr;
    if (s2 == nullptr) {
        cudaStreamCreateWithFlags(&s2, cudaStreamNonBlocking);
        cudaEventCreateWithFlags(&evW,   cudaEventDisableTiming);
        cudaEventCreateWithFlags(&evEnd, cudaEventDisableTiming);
    }

    // 0) weights + bias (s1); fork s2 after it.
    wbias_kernel<<<1024, 256>>>((const float4*)Wq, (const float4*)Wk,
                                (const float4*)Wv, (const float4*)Wo,
                                bq, bk, bv, (uint2*)wbase, bqkv);
    cudaEventRecord(evW, 0);
    cudaStreamWaitEvent(s2, evW, 0);

    // Chunked dual-stream pipeline: 4 self-contained quarter-batch chains.
    // Even chunks -> s1 (handle 0), odd chunks -> s2. No cross-chunk deps.
    for (int c = 0; c < 4; ++c) {
        cudaStream_t st = (c & 1) ? s2 : (cudaStream_t)0;
        const long oX  = (long)c * QB * CHW;          // xb / ob / out / x
        const long oQ  = (long)c * QB * QKVB;         // qkv
        const long oA  = (long)c * QB * SHW;          // ab
        const long oP  = (long)c * QB * HWD * 16;     // part
        const long oI  = (long)c * QB * HWD;          // inv

        // x convert for this chunk (QB batches)
        xcvt_kernel<<<512, 256, 0, st>>>((const float4*)(x + oX),
                                         (uint2*)(xb + oX),
                                         (int)(QB * CHW / 4));
        // QK projection
        {
            dim3 grd(HWD / 128, 2 * CDIM / 128, QB);
            kProj<<<grd, blk, SMEM, st>>>(wqkv, xb + oX, qkv + oQ, CDIM,
                                          0, CHW, QKVB,
                                          1.f, bqkv, nullptr, 0, nullptr);
        }
        // V projection
        {
            dim3 grd(HWD / 128, CDIM / 128, QB);
            kProj<<<grd, blk, SMEM, st>>>(wqkv + (long)2 * CDIM * CDIM, xb + oX,
                                          qkv + oQ + 2 * CHW, CDIM,
                                          0, CHW, QKVB,
                                          1.f, bqkv + 2 * CDIM, nullptr, 0, nullptr);
        }
        // scores + fused exp + partials
        {
            dim3 grd(HWD / 128, HWD / 128, QB);
            kScore<<<grd, blk, SMEM, st>>>(qkv + oQ, qkv + oQ + CHW, ab + oA,
                                           CDIM, QKVB, QKVB, SHW,
                                           alpha, nullptr, nullptr, 0, part + oP);
        }
        // 1/rowsum
        rowsum_inv_kernel<<<QB * HWD / 256, 256, 0, st>>>(
            (const float4*)(part + oP), inv + oI);
        // attn @ V (normalized)
        {
            dim3 grd(HWD / 128, CDIM / 128, QB);
            kAV<<<grd, blk, SMEM, st>>>(qkv + oQ + 2 * CHW, ab + oA, ob + oX,
                                        HWD, QKVB, SHW, CHW,
                                        1.f, nullptr, nullptr, 0, inv + oI);
        }
        // output projection + bias + residual
        {
            dim3 grd(HWD / 128, CDIM / 128, QB);
            kOut<<<grd, blk, SMEM, st>>>(wo, ob + oX, out + oX, CDIM,
                                         0, CHW, CHW,
                                         1.f, bo, x + oX, CHW, nullptr);
        }
    }

    // Join s2 back into s1 before capture ends.
    cudaEventRecord(evEnd, s2);
    cudaStreamWaitEvent((cudaStream_t)0, evEnd, 0);
}